// round 13
// baseline (speedup 1.0000x reference)
#include <cuda_runtime.h>
#include <cuda_bf16.h>
#include <math.h>
#include <stdint.h>

#define NE    16
#define TILE  128
#define KCB   128            // BYTES of K per chunk per row (128 e4m3 elems)
#define NSTAGE 2
#define BDIM  512            // 16 warps, 4x4 warp grid, 32x32 per warp
#define PBDIM 256
#define HDIM  1024
#define BROWS 4096

// ---- smem layout (bytes) ---------------------------------------------------
// Mainloop: 2 stages x (A 16KB + B 16KB) = 65536.
// Epilogue: pq tiles (8 x 4096 = 32KB) OVERLAY stage 0 (cp.async during last chunk).
#define STAGE_BYTES (2 * TILE * KCB)          // 32768
#define PQ_OFF     0                          // overlay
#define NEI_OFF    (NSTAGE * STAGE_BYTES)     // 65536
#define NEJ_OFF    (NEI_OFF + 512)
#define SMEM_BYTES (NEJ_OFF + 512)            // 66560 (2 CTAs/SM)

// pq tile order: 0 lpI_hi, 1 lpI_lo, 2 qI_hi, 3 qI_lo, 4 lpJ_hi, 5 lpJ_lo, 6 qJ_hi, 7 qJ_lo

// ---- device scratch (static zero-init; re-zeroed by last pairs block) -----
__device__ __align__(16) uint32_t g_nemb8[BROWS * (HDIM / 4)];  // e4m3 x16 scaled
__device__ __align__(16) __nv_bfloat16 g_pq[BROWS * 64];  // lp_hi|lp_lo|q_hi|q_lo
__device__ float g_negent[BROWS];
__device__ float g_cons, g_ent, g_eff;
__device__ float g_usage[NE];
__device__ unsigned long long g_pairs;
__device__ unsigned int g_done;

// ---- helpers ---------------------------------------------------------------
__device__ __forceinline__ uint32_t smem_u32(const void* p) {
    uint32_t a;
    asm("{ .reg .u64 t; cvta.to.shared.u64 t, %1; cvt.u32.u64 %0, t; }" : "=r"(a) : "l"(p));
    return a;
}
__device__ __forceinline__ void ldsm4(uint32_t (&r)[4], uint32_t addr) {
    asm volatile("ldmatrix.sync.aligned.m8n8.x4.shared.b16 {%0,%1,%2,%3}, [%4];"
                 : "=r"(r[0]), "=r"(r[1]), "=r"(r[2]), "=r"(r[3]) : "r"(addr));
}
// bf16 K=16 (epilogue KL dots)
__device__ __forceinline__ void mma16816(float (&d)[4], const uint32_t (&a)[4],
                                         uint32_t b0, uint32_t b1) {
    asm volatile("mma.sync.aligned.m16n8k16.row.col.f32.bf16.bf16.f32 "
        "{%0,%1,%2,%3}, {%4,%5,%6,%7}, {%8,%9}, {%0,%1,%2,%3};"
        : "+f"(d[0]), "+f"(d[1]), "+f"(d[2]), "+f"(d[3])
        : "r"(a[0]), "r"(a[1]), "r"(a[2]), "r"(a[3]), "r"(b0), "r"(b1));
}
// e4m3 K=32 (mainloop gram)
__device__ __forceinline__ void mma16832e4(float (&d)[4], const uint32_t (&a)[4],
                                           uint32_t b0, uint32_t b1) {
    asm volatile("mma.sync.aligned.m16n8k32.row.col.f32.e4m3.e4m3.f32 "
        "{%0,%1,%2,%3}, {%4,%5,%6,%7}, {%8,%9}, {%0,%1,%2,%3};"
        : "+f"(d[0]), "+f"(d[1]), "+f"(d[2]), "+f"(d[3])
        : "r"(a[0]), "r"(a[1]), "r"(a[2]), "r"(a[3]), "r"(b0), "r"(b1));
}
__device__ __forceinline__ uint32_t pack_e4m3x4(float e0, float e1, float e2, float e3) {
    uint16_t lo, hi;   // cvt packs: d = {a_hi_byte, b_lo_byte}
    asm("cvt.rn.satfinite.e4m3x2.f32 %0, %1, %2;" : "=h"(lo) : "f"(e1), "f"(e0));
    asm("cvt.rn.satfinite.e4m3x2.f32 %0, %1, %2;" : "=h"(hi) : "f"(e3), "f"(e2));
    return (uint32_t)lo | ((uint32_t)hi << 16);
}
#define CP_ASYNC16(sa, ga) \
    asm volatile("cp.async.cg.shared.global [%0], [%1], 16;" :: "r"(sa), "l"(ga) : "memory")
#define CP_COMMIT()  asm volatile("cp.async.commit_group;" ::: "memory")
#define CP_WAIT0()   asm volatile("cp.async.wait_group 0;" ::: "memory")

// ---------------------------------------------------------------------------
// One warp per row: softmax stats, hi/lo bf16 splits, normalized e4m3
// embeddings (x16 scale), plus block-reduced usage/entropy/efficiency.
__global__ void __launch_bounds__(PBDIM)
prep_kernel(const float* __restrict__ rp, const float* __restrict__ emb,
            int B, int H) {
    __shared__ float s_usage[NE];
    __shared__ float s_ent, s_eff;
    int tid = threadIdx.x;
    if (tid < NE) s_usage[tid] = 0.f;
    if (tid == 0) { s_ent = 0.f; s_eff = 0.f; }
    __syncthreads();

    int lane = tid & 31;
    int row  = blockIdx.x * (PBDIM / 32) + (tid >> 5);

    const float* prow = rp + (size_t)row * NE;
    float p  = (lane < NE) ? prow[lane] : 0.f;
    float pm = (lane < NE) ? p : -1e30f;
    #pragma unroll
    for (int o = 8; o; o >>= 1) pm = fmaxf(pm, __shfl_xor_sync(0xffffffffu, pm, o));
    float ex = (lane < NE) ? expf(p - pm) : 0.f;
    float s  = ex;
    #pragma unroll
    for (int o = 8; o; o >>= 1) s += __shfl_xor_sync(0xffffffffu, s, o);
    float lse = logf(s);
    float lp  = p - pm - lse;
    float qv  = expf(lp);
    float ne   = (lane < NE) ? qv * lp : 0.f;
    float entp = (lane < NE) ? p * logf(p + 1e-8f) : 0.f;
    float effp = (lane < NE && p < 0.1f) ? p : 0.f;
    #pragma unroll
    for (int o = 8; o; o >>= 1) {
        ne   += __shfl_xor_sync(0xffffffffu, ne, o);
        entp += __shfl_xor_sync(0xffffffffu, entp, o);
        effp += __shfl_xor_sync(0xffffffffu, effp, o);
    }
    if (lane < NE) {
        __nv_bfloat16 lph = __float2bfloat16(lp);
        __nv_bfloat16 lpl = __float2bfloat16(lp - __bfloat162float(lph));
        __nv_bfloat16 qh  = __float2bfloat16(qv);
        __nv_bfloat16 ql  = __float2bfloat16(qv - __bfloat162float(qh));
        size_t b = (size_t)row * 64;
        g_pq[b + lane]      = lph;
        g_pq[b + 16 + lane] = lpl;
        g_pq[b + 32 + lane] = qh;
        g_pq[b + 48 + lane] = ql;
        atomicAdd(&s_usage[lane], p);
    }
    if (lane == 0) {
        g_negent[row] = ne;
        atomicAdd(&s_ent, entp);
        atomicAdd(&s_eff, effp);
    }

    // normalize embedding -> e4m3 (x16 scale; sim scaled x256, sign intact)
    const float4* erow4 = (const float4*)(emb + (size_t)row * H);
    float4 v[8];
    float ss = 0.f;
    #pragma unroll
    for (int i = 0; i < 8; ++i) {
        v[i] = erow4[lane + i * 32];
        ss += v[i].x * v[i].x + v[i].y * v[i].y + v[i].z * v[i].z + v[i].w * v[i].w;
    }
    #pragma unroll
    for (int o = 16; o; o >>= 1) ss += __shfl_xor_sync(0xffffffffu, ss, o);
    float inv = 16.f / sqrtf(ss);
    uint32_t* nrow = g_nemb8 + (size_t)row * (HDIM / 4);
    #pragma unroll
    for (int i = 0; i < 8; ++i) {
        nrow[lane + i * 32] = pack_e4m3x4(v[i].x * inv, v[i].y * inv,
                                          v[i].z * inv, v[i].w * inv);
    }

    __syncthreads();
    if (tid < NE) atomicAdd(&g_usage[tid], s_usage[tid]);
    if (tid == 0) { atomicAdd(&g_ent, s_ent); atomicAdd(&g_eff, s_eff); }
}

// ---------------------------------------------------------------------------
// Per 128x128 tile (upper triangle): e4m3 K=32 mma gram + masked bf16 KL
// epilogue. 16 warps in 4(M) x 4(N) grid, 32x32 per warp; 2-stage cp.async;
// 2 CTAs/SM (regs capped 64) -> 32 warps/SM.
// Last block to finish computes the final loss and re-zeros global state.
__global__ void __launch_bounds__(BDIM, 2)
pairs_kernel(int B, int H, float* __restrict__ out, int ntiles) {
    extern __shared__ char smem[];
    uint32_t sb = smem_u32(smem);
    const int tid  = threadIdx.x;
    const int wid  = tid >> 5;
    const int lane = tid & 31;
    const int wm   = wid >> 2;       // 0..3 (M)
    const int wn   = wid & 3;        // 0..3 (N)

    int nT = B / TILE;
    int I = 0, rem = blockIdx.x;
    while (rem >= nT - I) { rem -= nT - I; I++; }
    int J = I + rem;                 // I <= J

    if (tid < TILE) {
        *(float*)(smem + NEI_OFF + tid * 4) = g_negent[I * TILE + tid];
        *(float*)(smem + NEJ_OFF + tid * 4) = g_negent[J * TILE + tid];
    }

    const uint8_t* Agb = (const uint8_t*)g_nemb8 + (size_t)(I * TILE) * HDIM;
    const uint8_t* Bgb = (const uint8_t*)g_nemb8 + (size_t)(J * TILE) * HDIM;

    // chunk: 128 rows x 8 16B-units per matrix (128B = 128 e4m3 of K)
    auto load_chunk = [&](int c, int stage) {
        uint32_t soff = sb + stage * STAGE_BYTES;
        const uint8_t* Ag = Agb + c * KCB;
        const uint8_t* Bg = Bgb + c * KCB;
        #pragma unroll
        for (int k = 0; k < 4; ++k) {
            int idx = tid + k * BDIM;            // 0..2047
            int t = idx >> 10;                   // 0 = A, 1 = B
            int r = (idx >> 3) & 127;
            int u = idx & 7;
            const uint8_t* g = (t ? Bg : Ag) + (size_t)r * HDIM + u * 16;
            uint32_t sa = soff + t * 16384 + ((r * 8 + (u ^ (r & 7))) << 4);
            CP_ASYNC16(sa, g);
        }
    };

    float acc[2][4][4] = {};

    // XOR-affine ldsm addressing: fragment rows share c7 = lane&7, so
    // addr = S_f + (((2s) ^ v) << 4) with v = (lane>>4) ^ c7 hoisted.
    const int lrow = ((lane >> 3) & 1) * 8 + (lane & 7);   // row offset within 16
    const uint32_t vx = ((uint32_t)(lane >> 4)) ^ ((uint32_t)(lane & 7));
    const uint32_t SA0 = (uint32_t)(wm * 32 + lrow) * 128;          // +2048 for f=1
    const uint32_t SB0 = 16384u + (uint32_t)(wn * 32 + lrow) * 128; // +2048 for nb=1

    auto compute_chunk = [&](int stage) {
        uint32_t sbase = sb + stage * STAGE_BYTES;
        #pragma unroll
        for (int s = 0; s < 4; ++s) {          // 4 K=32 steps (32B each)
            uint32_t w = (((uint32_t)(2 * s)) ^ vx) << 4;
            uint32_t af[2][4];
            ldsm4(af[0], sbase + SA0 + w);
            ldsm4(af[1], sbase + SA0 + 2048 + w);
            uint32_t bfr[2][4];
            ldsm4(bfr[0], sbase + SB0 + w);
            ldsm4(bfr[1], sbase + SB0 + 2048 + w);
            #pragma unroll
            for (int f = 0; f < 2; ++f)
                #pragma unroll
                for (int nb = 0; nb < 2; ++nb) {
                    mma16832e4(acc[f][nb * 2 + 0], af[f], bfr[nb][0], bfr[nb][2]);
                    mma16832e4(acc[f][nb * 2 + 1], af[f], bfr[nb][1], bfr[nb][3]);
                }
        }
    };

    const int NCHUNK = HDIM / KCB;   // 8
    load_chunk(0, 0); CP_COMMIT();
    #pragma unroll 1
    for (int c = 0; c < NCHUNK; ++c) {
        CP_WAIT0();
        __syncthreads();             // chunk c visible; all warps done with stage (c-1)&1
        if (c + 1 < NCHUNK) {
            load_chunk(c + 1, (c + 1) & 1);
            CP_COMMIT();
        } else {
            // stage pq tiles into the (now free) stage-0 overlay via cp.async,
            // overlapped with the final chunk's compute.
            const uint8_t* pqI = (const uint8_t*)(g_pq + (size_t)(I * TILE) * 64);
            const uint8_t* pqJ = (const uint8_t*)(g_pq + (size_t)(J * TILE) * 64);
            #pragma unroll
            for (int k = 0; k < 4; ++k) {
                int idx = tid + k * BDIM;        // 0..2047
                int side = idx >> 10;            // 0 = I, 1 = J
                int r2   = idx & 1023;
                int r    = r2 >> 3;
                int s    = r2 & 7;
                int sec = s >> 1, half = s & 1;  // 0 lp_hi, 1 lp_lo, 2 q_hi, 3 q_lo
                const uint8_t* src = (side ? pqJ : pqI) + r * 128 + sec * 32 + half * 16;
                uint32_t dst = sb + PQ_OFF + (uint32_t)(side * 4 + sec) * 4096
                             + (uint32_t)r * 32 + (uint32_t)half * 16;
                CP_ASYNC16(dst, src);
            }
            CP_COMMIT();
        }
        compute_chunk(c & 1);
    }
    CP_WAIT0();                      // pq staging landed
    __syncthreads();

    // ---- epilogue: mask from sim sign, ne sums, then mma KL dots ----------
    const float* neI = (const float*)(smem + NEI_OFF);
    const float* neJ = (const float*)(smem + NEJ_OFF);
    int g  = lane >> 2, tg = lane & 3;
    uint32_t mask = 0u;
    float cons = 0.f;
    #pragma unroll
    for (int f = 0; f < 2; ++f) {
        int rl = wm * 32 + f * 16 + g;
        #pragma unroll
        for (int n8 = 0; n8 < 4; ++n8) {
            int c0 = wn * 32 + n8 * 8 + tg * 2;
            #pragma unroll
            for (int ci = 0; ci < 4; ++ci) {
                int rr = rl + (ci >> 1) * 8;
                int cc = c0 + (ci & 1);
                if (acc[f][n8][ci] > 0.f && (I != J || rr < cc)) {
                    mask |= 1u << ((f * 4 + n8) * 4 + ci);
                    cons += neI[rr] + neJ[cc];
                }
            }
        }
    }
    int cnt = 2 * __popc(mask);      // ordered pairs

    // K=16 bf16 mma pass over pq tiles (32B row stride)
    auto pq_pass = [&](int atile, int btile, float (*kl)[4][4]) {
        uint32_t ab = sb + PQ_OFF + atile * 4096;
        uint32_t bb = sb + PQ_OFF + btile * 4096;
        int lu16 = (lane >> 4) * 16;
        uint32_t af[2][4];
        #pragma unroll
        for (int f = 0; f < 2; ++f)
            ldsm4(af[f], ab + (wm * 32 + f * 16 + lrow) * 32 + lu16);
        #pragma unroll
        for (int nb = 0; nb < 2; ++nb) {
            uint32_t b4[4];
            ldsm4(b4, bb + (wn * 32 + nb * 16 + lrow) * 32 + lu16);
            #pragma unroll
            for (int f = 0; f < 2; ++f) {
                mma16816(kl[f][nb * 2 + 0], af[f], b4[0], b4[2]);
                mma16816(kl[f][nb * 2 + 1], af[f], b4[1], b4[3]);
            }
        }
    };

    {
        float kl[2][4][4] = {};
        pq_pass(0, 6, kl);   // lpI_hi . qJ_hi
        pq_pass(1, 6, kl);   // lpI_lo . qJ_hi
        pq_pass(0, 7, kl);   // lpI_hi . qJ_lo
        #pragma unroll
        for (int f = 0; f < 2; ++f)
            #pragma unroll
            for (int n8 = 0; n8 < 4; ++n8)
                #pragma unroll
                for (int ci = 0; ci < 4; ++ci) {
                    if ((mask >> ((f * 4 + n8) * 4 + ci)) & 1u)
                        cons -= kl[f][n8][ci];
                    kl[f][n8][ci] = 0.f;
                }
        pq_pass(2, 4, kl);   // qI_hi . lpJ_hi
        pq_pass(3, 4, kl);   // qI_lo . lpJ_hi
        pq_pass(2, 5, kl);   // qI_hi . lpJ_lo
        #pragma unroll
        for (int f = 0; f < 2; ++f)
            #pragma unroll
            for (int n8 = 0; n8 < 4; ++n8)
                #pragma unroll
                for (int ci = 0; ci < 4; ++ci)
                    if ((mask >> ((f * 4 + n8) * 4 + ci)) & 1u)
                        cons -= kl[f][n8][ci];
    }

    // ---- block reduce + atomics -------------------------------------------
    #pragma unroll
    for (int o = 16; o; o >>= 1) {
        cons += __shfl_xor_sync(0xffffffffu, cons, o);
        cnt  += __shfl_xor_sync(0xffffffffu, cnt, o);
    }
    __shared__ float wsum[16];
    __shared__ int   wcnt[16];
    __shared__ int   s_last;
    if (lane == 0) { wsum[wid] = cons; wcnt[wid] = cnt; }
    __syncthreads();
    if (tid == 0) {
        float cs = 0.f; int cc = 0;
        #pragma unroll
        for (int w = 0; w < 16; w++) { cs += wsum[w]; cc += wcnt[w]; }
        atomicAdd(&g_cons, cs);
        atomicAdd(&g_pairs, (unsigned long long)cc);
        __threadfence();
        unsigned int old = atomicAdd(&g_done, 1u);
        s_last = (old == (unsigned int)(ntiles - 1));
    }
    __syncthreads();

    // ---- last block: finalize + re-zero state for the next replay ---------
    if (s_last && tid == 0) {
        float invB = 1.f / (float)B;
        float u[NE], mean = 0.f;
        #pragma unroll
        for (int e = 0; e < NE; e++) { u[e] = g_usage[e] * invB; mean += u[e]; }
        mean /= (float)NE;
        float var = 0.f;
        #pragma unroll
        for (int e = 0; e < NE; e++) { float d = u[e] - mean; var += d * d; }
        var /= (float)(NE - 1);
        float load_balance = var * (float)(NE * NE);
        float entropy_loss = g_ent * invB;
        float efficiency   = g_eff * invB;
        unsigned long long np = g_pairs;
        float consf = (np > 0) ? (g_cons / (float)np) : 0.f;
        out[0] = load_balance + entropy_loss + efficiency + consf;
        // reset accumulators so every graph replay starts clean
        g_cons = 0.f; g_ent = 0.f; g_eff = 0.f; g_pairs = 0ull;
        #pragma unroll
        for (int e = 0; e < NE; e++) g_usage[e] = 0.f;
        g_done = 0u;
    }
}

// ---------------------------------------------------------------------------
extern "C" void kernel_launch(void* const* d_in, const int* in_sizes, int n_in,
                              void* d_out, int out_size) {
    const float* rp  = (const float*)d_in[0];
    const float* emb = (const float*)d_in[1];
    float* out = (float*)d_out;
    int B = in_sizes[0] / NE;        // 4096
    int H = in_sizes[1] / B;         // 1024

    cudaFuncSetAttribute(pairs_kernel,
                         cudaFuncAttributeMaxDynamicSharedMemorySize, SMEM_BYTES);

    prep_kernel<<<B / (PBDIM / 32), PBDIM>>>(rp, emb, B, H);
    int nT = B / TILE;
    int ntiles = nT * (nT + 1) / 2;  // 528
    pairs_kernel<<<ntiles, BDIM, SMEM_BYTES>>>(B, H, out, ntiles);
}

// round 15
// speedup vs baseline: 1.2875x; 1.2875x over previous
#include <cuda_runtime.h>
#include <cuda_bf16.h>
#include <math.h>
#include <stdint.h>

#define NE    16
#define TILE  128
#define KCB   128            // BYTES of K per chunk per row (128 e4m3 elems)
#define NSTAGE 2
#define BDIM  256
#define HDIM  1024
#define BROWS 4096

// ---- smem layout (bytes) ---------------------------------------------------
// Mainloop: 2 stages x (A 16KB + B 16KB) = 65536.
// Epilogue: pq tiles (8 x 4096 = 32KB) OVERLAY stage 0 (cp.async during last chunk).
#define STAGE_BYTES (2 * TILE * KCB)          // 32768
#define PQ_OFF     0                          // overlay
#define NEI_OFF    (NSTAGE * STAGE_BYTES)     // 65536
#define NEJ_OFF    (NEI_OFF + 512)
#define SMEM_BYTES (NEJ_OFF + 512)            // 66560  (2 CTAs/SM)

// pq tile order: 0 lpI_hi, 1 lpI_lo, 2 qI_hi, 3 qI_lo, 4 lpJ_hi, 5 lpJ_lo, 6 qJ_hi, 7 qJ_lo

// ---- device scratch (static zero-init; re-zeroed by last pairs block) -----
__device__ __align__(16) uint32_t g_nemb8[BROWS * (HDIM / 4)];  // e4m3 x16 scaled
__device__ __align__(16) __nv_bfloat16 g_pq[BROWS * 64];  // lp_hi|lp_lo|q_hi|q_lo
__device__ float g_negent[BROWS];
__device__ float g_cons, g_ent, g_eff;
__device__ float g_usage[NE];
__device__ unsigned long long g_pairs;
__device__ unsigned int g_done;

// ---- helpers ---------------------------------------------------------------
__device__ __forceinline__ uint32_t smem_u32(const void* p) {
    uint32_t a;
    asm("{ .reg .u64 t; cvta.to.shared.u64 t, %1; cvt.u32.u64 %0, t; }" : "=r"(a) : "l"(p));
    return a;
}
__device__ __forceinline__ void ldsm4(uint32_t (&r)[4], uint32_t addr) {
    asm volatile("ldmatrix.sync.aligned.m8n8.x4.shared.b16 {%0,%1,%2,%3}, [%4];"
                 : "=r"(r[0]), "=r"(r[1]), "=r"(r[2]), "=r"(r[3]) : "r"(addr));
}
// bf16 K=16 (epilogue KL dots)
__device__ __forceinline__ void mma16816(float (&d)[4], const uint32_t (&a)[4],
                                         uint32_t b0, uint32_t b1) {
    asm volatile("mma.sync.aligned.m16n8k16.row.col.f32.bf16.bf16.f32 "
        "{%0,%1,%2,%3}, {%4,%5,%6,%7}, {%8,%9}, {%0,%1,%2,%3};"
        : "+f"(d[0]), "+f"(d[1]), "+f"(d[2]), "+f"(d[3])
        : "r"(a[0]), "r"(a[1]), "r"(a[2]), "r"(a[3]), "r"(b0), "r"(b1));
}
// e4m3 K=32 (mainloop gram)
__device__ __forceinline__ void mma16832e4(float (&d)[4], const uint32_t (&a)[4],
                                           uint32_t b0, uint32_t b1) {
    asm volatile("mma.sync.aligned.m16n8k32.row.col.f32.e4m3.e4m3.f32 "
        "{%0,%1,%2,%3}, {%4,%5,%6,%7}, {%8,%9}, {%0,%1,%2,%3};"
        : "+f"(d[0]), "+f"(d[1]), "+f"(d[2]), "+f"(d[3])
        : "r"(a[0]), "r"(a[1]), "r"(a[2]), "r"(a[3]), "r"(b0), "r"(b1));
}
__device__ __forceinline__ uint32_t pack_e4m3x4(float e0, float e1, float e2, float e3) {
    uint16_t lo, hi;   // cvt packs: d = {a_hi_byte, b_lo_byte}
    asm("cvt.rn.satfinite.e4m3x2.f32 %0, %1, %2;" : "=h"(lo) : "f"(e1), "f"(e0));
    asm("cvt.rn.satfinite.e4m3x2.f32 %0, %1, %2;" : "=h"(hi) : "f"(e3), "f"(e2));
    return (uint32_t)lo | ((uint32_t)hi << 16);
}
#define CP_ASYNC16(sa, ga) \
    asm volatile("cp.async.cg.shared.global [%0], [%1], 16;" :: "r"(sa), "l"(ga) : "memory")
#define CP_COMMIT()  asm volatile("cp.async.commit_group;" ::: "memory")
#define CP_WAIT0()   asm volatile("cp.async.wait_group 0;" ::: "memory")

// ---------------------------------------------------------------------------
// One warp per row: softmax stats, hi/lo bf16 splits, normalized e4m3
// embeddings (x16 scale), plus block-reduced usage/entropy/efficiency.
__global__ void __launch_bounds__(BDIM)
prep_kernel(const float* __restrict__ rp, const float* __restrict__ emb,
            int B, int H) {
    __shared__ float s_usage[NE];
    __shared__ float s_ent, s_eff;
    int tid = threadIdx.x;
    if (tid < NE) s_usage[tid] = 0.f;
    if (tid == 0) { s_ent = 0.f; s_eff = 0.f; }
    __syncthreads();

    int lane = tid & 31;
    int row  = blockIdx.x * (BDIM / 32) + (tid >> 5);

    const float* prow = rp + (size_t)row * NE;
    float p  = (lane < NE) ? prow[lane] : 0.f;
    float pm = (lane < NE) ? p : -1e30f;
    #pragma unroll
    for (int o = 8; o; o >>= 1) pm = fmaxf(pm, __shfl_xor_sync(0xffffffffu, pm, o));
    float ex = (lane < NE) ? expf(p - pm) : 0.f;
    float s  = ex;
    #pragma unroll
    for (int o = 8; o; o >>= 1) s += __shfl_xor_sync(0xffffffffu, s, o);
    float lse = logf(s);
    float lp  = p - pm - lse;
    float qv  = expf(lp);
    float ne   = (lane < NE) ? qv * lp : 0.f;
    float entp = (lane < NE) ? p * logf(p + 1e-8f) : 0.f;
    float effp = (lane < NE && p < 0.1f) ? p : 0.f;
    #pragma unroll
    for (int o = 8; o; o >>= 1) {
        ne   += __shfl_xor_sync(0xffffffffu, ne, o);
        entp += __shfl_xor_sync(0xffffffffu, entp, o);
        effp += __shfl_xor_sync(0xffffffffu, effp, o);
    }
    if (lane < NE) {
        __nv_bfloat16 lph = __float2bfloat16(lp);
        __nv_bfloat16 lpl = __float2bfloat16(lp - __bfloat162float(lph));
        __nv_bfloat16 qh  = __float2bfloat16(qv);
        __nv_bfloat16 ql  = __float2bfloat16(qv - __bfloat162float(qh));
        size_t b = (size_t)row * 64;
        g_pq[b + lane]      = lph;
        g_pq[b + 16 + lane] = lpl;
        g_pq[b + 32 + lane] = qh;
        g_pq[b + 48 + lane] = ql;
        atomicAdd(&s_usage[lane], p);
    }
    if (lane == 0) {
        g_negent[row] = ne;
        atomicAdd(&s_ent, entp);
        atomicAdd(&s_eff, effp);
    }

    // normalize embedding -> e4m3 (x16 scale; sim scaled x256, sign intact)
    const float4* erow4 = (const float4*)(emb + (size_t)row * H);
    float4 v[8];
    float ss = 0.f;
    #pragma unroll
    for (int i = 0; i < 8; ++i) {
        v[i] = erow4[lane + i * 32];
        ss += v[i].x * v[i].x + v[i].y * v[i].y + v[i].z * v[i].z + v[i].w * v[i].w;
    }
    #pragma unroll
    for (int o = 16; o; o >>= 1) ss += __shfl_xor_sync(0xffffffffu, ss, o);
    float inv = 16.f / sqrtf(ss);
    uint32_t* nrow = g_nemb8 + (size_t)row * (HDIM / 4);
    #pragma unroll
    for (int i = 0; i < 8; ++i) {
        nrow[lane + i * 32] = pack_e4m3x4(v[i].x * inv, v[i].y * inv,
                                          v[i].z * inv, v[i].w * inv);
    }

    __syncthreads();
    if (tid < NE) atomicAdd(&g_usage[tid], s_usage[tid]);
    if (tid == 0) { atomicAdd(&g_ent, s_ent); atomicAdd(&g_eff, s_eff); }
}

// ---------------------------------------------------------------------------
// Per 128x128 tile (upper triangle): e4m3 K=32 mma gram + masked bf16 KL
// epilogue. 8 warps in 4(M) x 2(N) grid, 32x64 per warp; 2-stage cp.async;
// 2 CTAs/SM. pq tiles staged via cp.async overlapped with the final chunk.
// Last block to finish computes the final loss and re-zeros global state.
__global__ void __launch_bounds__(BDIM, 2)
pairs_kernel(int B, int H, float* __restrict__ out, int ntiles) {
    extern __shared__ char smem[];
    uint32_t sb = smem_u32(smem);
    const int tid  = threadIdx.x;
    const int wid  = tid >> 5;
    const int lane = tid & 31;
    const int wm   = wid >> 1;       // 0..3 (M)
    const int wn   = wid & 1;        // 0..1 (N)

    int nT = B / TILE;
    int I = 0, rem = blockIdx.x;
    while (rem >= nT - I) { rem -= nT - I; I++; }
    int J = I + rem;                 // I <= J

    if (tid < TILE) {
        *(float*)(smem + NEI_OFF + tid * 4) = g_negent[I * TILE + tid];
        *(float*)(smem + NEJ_OFF + tid * 4) = g_negent[J * TILE + tid];
    }

    const uint8_t* Agb = (const uint8_t*)g_nemb8 + (size_t)(I * TILE) * HDIM;
    const uint8_t* Bgb = (const uint8_t*)g_nemb8 + (size_t)(J * TILE) * HDIM;

    // chunk: 128 rows x 8 16B-units per matrix (128B = 128 e4m3 of K)
    auto load_chunk = [&](int c, int stage) {
        uint32_t soff = sb + stage * STAGE_BYTES;
        const uint8_t* Ag = Agb + c * KCB;
        const uint8_t* Bg = Bgb + c * KCB;
        #pragma unroll
        for (int k = 0; k < 8; ++k) {
            int idx = tid + k * BDIM;            // 0..2047
            int t = idx >> 10;                   // 0 = A, 1 = B
            int r = (idx >> 3) & 127;
            int u = idx & 7;
            const uint8_t* g = (t ? Bg : Ag) + (size_t)r * HDIM + u * 16;
            uint32_t sa = soff + t * 16384 + ((r * 8 + (u ^ (r & 7))) << 4);
            CP_ASYNC16(sa, g);
        }
    };

    float acc[2][8][4] = {};

    auto compute_chunk = [&](int stage) {
        uint32_t abase = sb + stage * STAGE_BYTES;
        uint32_t bbase = abase + 16384;
        int lrow = ((lane >> 3) & 1) * 8 + (lane & 7);   // row offset within 16
        int lu   = lane >> 4;                            // unit offset (0/1)
        #pragma unroll
        for (int s = 0; s < 4; ++s) {          // 4 K=32 steps (32B each)
            uint32_t af[2][4];
            #pragma unroll
            for (int f = 0; f < 2; ++f) {
                int row = wm * 32 + f * 16 + lrow;
                int u = 2 * s + lu;
                ldsm4(af[f], abase + ((row * 8 + (u ^ (row & 7))) << 4));
            }
            uint32_t bfr[4][4];
            #pragma unroll
            for (int nb = 0; nb < 4; ++nb) {
                int row = wn * 64 + nb * 16 + lrow;
                int u = 2 * s + lu;
                ldsm4(bfr[nb], bbase + ((row * 8 + (u ^ (row & 7))) << 4));
            }
            #pragma unroll
            for (int f = 0; f < 2; ++f)
                #pragma unroll
                for (int nb = 0; nb < 4; ++nb) {
                    mma16832e4(acc[f][nb * 2 + 0], af[f], bfr[nb][0], bfr[nb][2]);
                    mma16832e4(acc[f][nb * 2 + 1], af[f], bfr[nb][1], bfr[nb][3]);
                }
        }
    };

    const int NCHUNK = HDIM / KCB;   // 8
    load_chunk(0, 0); CP_COMMIT();
    #pragma unroll 1
    for (int c = 0; c < NCHUNK; ++c) {
        CP_WAIT0();
        __syncthreads();             // chunk c visible; all warps done with stage (c-1)&1
        if (c + 1 < NCHUNK) {
            load_chunk(c + 1, (c + 1) & 1);
            CP_COMMIT();
        } else {
            // stage pq tiles into the (now free) stage-0 overlay via cp.async,
            // overlapped with the final chunk's compute. (Stage 0's last reader
            // was chunk NCHUNK-2, finished before the barrier above.)
            const uint8_t* pqI = (const uint8_t*)(g_pq + (size_t)(I * TILE) * 64);
            const uint8_t* pqJ = (const uint8_t*)(g_pq + (size_t)(J * TILE) * 64);
            #pragma unroll
            for (int k = 0; k < 8; ++k) {
                int idx = tid + k * BDIM;        // 0..2047
                int side = idx >> 10;            // 0 = I, 1 = J
                int r2   = idx & 1023;
                int r    = r2 >> 3;
                int s    = r2 & 7;
                int sec = s >> 1, half = s & 1;  // 0 lp_hi, 1 lp_lo, 2 q_hi, 3 q_lo
                const uint8_t* src = (side ? pqJ : pqI) + r * 128 + sec * 32 + half * 16;
                uint32_t dst = sb + PQ_OFF + (uint32_t)(side * 4 + sec) * 4096
                             + (uint32_t)r * 32 + (uint32_t)half * 16;
                CP_ASYNC16(dst, src);
            }
            CP_COMMIT();
        }
        compute_chunk(c & 1);
    }
    CP_WAIT0();                      // pq staging landed
    __syncthreads();

    // ---- epilogue: mask from sim sign, ne sums, then mma KL dots ----------
    const float* neI = (const float*)(smem + NEI_OFF);
    const float* neJ = (const float*)(smem + NEJ_OFF);
    int g  = lane >> 2, tg = lane & 3;
    uint64_t mask = 0ull;
    float cons = 0.f;
    #pragma unroll
    for (int f = 0; f < 2; ++f) {
        int rl = wm * 32 + f * 16 + g;
        #pragma unroll
        for (int n8 = 0; n8 < 8; ++n8) {
            int c0 = wn * 64 + n8 * 8 + tg * 2;
            #pragma unroll
            for (int ci = 0; ci < 4; ++ci) {
                int rr = rl + (ci >> 1) * 8;
                int cc = c0 + (ci & 1);
                if (acc[f][n8][ci] > 0.f && (I != J || rr < cc)) {
                    mask |= 1ull << ((f * 8 + n8) * 4 + ci);
                    cons += neI[rr] + neJ[cc];
                }
            }
        }
    }
    int cnt = 2 * __popcll(mask);    // ordered pairs

    // K=16 bf16 mma pass over pq tiles (32B row stride)
    auto pq_pass = [&](int atile, int btile, float (*kl)[8][4]) {
        uint32_t ab = sb + PQ_OFF + atile * 4096;
        uint32_t bb = sb + PQ_OFF + btile * 4096;
        int lrow = ((lane >> 3) & 1) * 8 + (lane & 7);
        int lu16 = (lane >> 4) * 16;
        uint32_t af[2][4];
        #pragma unroll
        for (int f = 0; f < 2; ++f) {
            int row = wm * 32 + f * 16 + lrow;
            ldsm4(af[f], ab + row * 32 + lu16);
        }
        #pragma unroll
        for (int nb = 0; nb < 4; ++nb) {
            uint32_t b4[4];
            int row = wn * 64 + nb * 16 + lrow;
            ldsm4(b4, bb + row * 32 + lu16);
            #pragma unroll
            for (int f = 0; f < 2; ++f) {
                mma16816(kl[f][nb * 2 + 0], af[f], b4[0], b4[2]);
                mma16816(kl[f][nb * 2 + 1], af[f], b4[1], b4[3]);
            }
        }
    };

    {
        float kl[2][8][4] = {};
        pq_pass(0, 6, kl);   // lpI_hi . qJ_hi
        pq_pass(1, 6, kl);   // lpI_lo . qJ_hi
        pq_pass(0, 7, kl);   // lpI_hi . qJ_lo
        #pragma unroll
        for (int f = 0; f < 2; ++f)
            #pragma unroll
            for (int n8 = 0; n8 < 8; ++n8)
                #pragma unroll
                for (int ci = 0; ci < 4; ++ci) {
                    if ((mask >> ((f * 8 + n8) * 4 + ci)) & 1ull)
                        cons -= kl[f][n8][ci];
                    kl[f][n8][ci] = 0.f;
                }
        pq_pass(2, 4, kl);   // qI_hi . lpJ_hi
        pq_pass(3, 4, kl);   // qI_lo . lpJ_hi
        pq_pass(2, 5, kl);   // qI_hi . lpJ_lo
        #pragma unroll
        for (int f = 0; f < 2; ++f)
            #pragma unroll
            for (int n8 = 0; n8 < 8; ++n8)
                #pragma unroll
                for (int ci = 0; ci < 4; ++ci)
                    if ((mask >> ((f * 8 + n8) * 4 + ci)) & 1ull)
                        cons -= kl[f][n8][ci];
    }

    // ---- block reduce + atomics -------------------------------------------
    #pragma unroll
    for (int o = 16; o; o >>= 1) {
        cons += __shfl_xor_sync(0xffffffffu, cons, o);
        cnt  += __shfl_xor_sync(0xffffffffu, cnt, o);
    }
    __shared__ float wsum[8];
    __shared__ int   wcnt[8];
    __shared__ int   s_last;
    if (lane == 0) { wsum[wid] = cons; wcnt[wid] = cnt; }
    __syncthreads();
    if (tid == 0) {
        float cs = 0.f; int cc = 0;
        #pragma unroll
        for (int w = 0; w < 8; w++) { cs += wsum[w]; cc += wcnt[w]; }
        atomicAdd(&g_cons, cs);
        atomicAdd(&g_pairs, (unsigned long long)cc);
        __threadfence();
        unsigned int old = atomicAdd(&g_done, 1u);
        s_last = (old == (unsigned int)(ntiles - 1));
    }
    __syncthreads();

    // ---- last block: finalize + re-zero state for the next replay ---------
    if (s_last && tid == 0) {
        float invB = 1.f / (float)B;
        float u[NE], mean = 0.f;
        #pragma unroll
        for (int e = 0; e < NE; e++) { u[e] = g_usage[e] * invB; mean += u[e]; }
        mean /= (float)NE;
        float var = 0.f;
        #pragma unroll
        for (int e = 0; e < NE; e++) { float d = u[e] - mean; var += d * d; }
        var /= (float)(NE - 1);
        float load_balance = var * (float)(NE * NE);
        float entropy_loss = g_ent * invB;
        float efficiency   = g_eff * invB;
        unsigned long long np = g_pairs;
        float consf = (np > 0) ? (g_cons / (float)np) : 0.f;
        out[0] = load_balance + entropy_loss + efficiency + consf;
        // reset accumulators so every graph replay starts clean
        g_cons = 0.f; g_ent = 0.f; g_eff = 0.f; g_pairs = 0ull;
        #pragma unroll
        for (int e = 0; e < NE; e++) g_usage[e] = 0.f;
        g_done = 0u;
    }
}

// ---------------------------------------------------------------------------
extern "C" void kernel_launch(void* const* d_in, const int* in_sizes, int n_in,
                              void* d_out, int out_size) {
    const float* rp  = (const float*)d_in[0];
    const float* emb = (const float*)d_in[1];
    float* out = (float*)d_out;
    int B = in_sizes[0] / NE;        // 4096
    int H = in_sizes[1] / B;         // 1024

    cudaFuncSetAttribute(pairs_kernel,
                         cudaFuncAttributeMaxDynamicSharedMemorySize, SMEM_BYTES);

    prep_kernel<<<B / (BDIM / 32), BDIM>>>(rp, emb, B, H);
    int nT = B / TILE;
    int ntiles = nT * (nT + 1) / 2;  // 528
    pairs_kernel<<<ntiles, BDIM, SMEM_BYTES>>>(B, H, out, ntiles);
}

// round 16
// speedup vs baseline: 1.3374x; 1.0388x over previous
#include <cuda_runtime.h>
#include <cuda_bf16.h>
#include <math.h>
#include <stdint.h>

#define NE    16
#define TILE  128
#define KCB   128            // BYTES of K per chunk per row (128 e4m3 elems)
#define NSTAGE 2
#define BDIM  256
#define HDIM  1024
#define BROWS 4096
#define MAXCTAS 304          // >= 2 x 152 SMs (GB300)

// ---- smem layout (bytes) ---------------------------------------------------
#define STAGE_BYTES (2 * TILE * KCB)          // 32768
#define PQ_OFF     0                          // overlay stage 0 (after mainloop)
#define NEI_OFF    (NSTAGE * STAGE_BYTES)     // 65536
#define NEJ_OFF    (NEI_OFF + 512)
#define SMEM_BYTES (NEJ_OFF + 512)            // 66560  (2 CTAs/SM)

// pq tile order: 0 lpI_hi, 1 lpI_lo, 2 qI_hi, 3 qI_lo, 4 lpJ_hi, 5 lpJ_lo, 6 qJ_hi, 7 qJ_lo

// ---- device scratch (static zero-init; re-zeroed by last pairs block) -----
__device__ __align__(16) uint32_t g_nemb8[BROWS * (HDIM / 4)];  // e4m3 x16 scaled
__device__ __align__(16) __nv_bfloat16 g_pq[BROWS * 64];  // lp_hi|lp_lo|q_hi|q_lo
__device__ float g_negent[BROWS];
__device__ float g_cons, g_ent, g_eff;
__device__ float g_usage[NE];
__device__ unsigned long long g_pairs;
__device__ unsigned int g_done;

// ---- helpers ---------------------------------------------------------------
__device__ __forceinline__ uint32_t smem_u32(const void* p) {
    uint32_t a;
    asm("{ .reg .u64 t; cvta.to.shared.u64 t, %1; cvt.u32.u64 %0, t; }" : "=r"(a) : "l"(p));
    return a;
}
__device__ __forceinline__ void ldsm4(uint32_t (&r)[4], uint32_t addr) {
    asm volatile("ldmatrix.sync.aligned.m8n8.x4.shared.b16 {%0,%1,%2,%3}, [%4];"
                 : "=r"(r[0]), "=r"(r[1]), "=r"(r[2]), "=r"(r[3]) : "r"(addr));
}
// bf16 K=16 (epilogue KL dots)
__device__ __forceinline__ void mma16816(float (&d)[4], const uint32_t (&a)[4],
                                         uint32_t b0, uint32_t b1) {
    asm volatile("mma.sync.aligned.m16n8k16.row.col.f32.bf16.bf16.f32 "
        "{%0,%1,%2,%3}, {%4,%5,%6,%7}, {%8,%9}, {%0,%1,%2,%3};"
        : "+f"(d[0]), "+f"(d[1]), "+f"(d[2]), "+f"(d[3])
        : "r"(a[0]), "r"(a[1]), "r"(a[2]), "r"(a[3]), "r"(b0), "r"(b1));
}
// e4m3 K=32 (mainloop gram)
__device__ __forceinline__ void mma16832e4(float (&d)[4], const uint32_t (&a)[4],
                                           uint32_t b0, uint32_t b1) {
    asm volatile("mma.sync.aligned.m16n8k32.row.col.f32.e4m3.e4m3.f32 "
        "{%0,%1,%2,%3}, {%4,%5,%6,%7}, {%8,%9}, {%0,%1,%2,%3};"
        : "+f"(d[0]), "+f"(d[1]), "+f"(d[2]), "+f"(d[3])
        : "r"(a[0]), "r"(a[1]), "r"(a[2]), "r"(a[3]), "r"(b0), "r"(b1));
}
__device__ __forceinline__ uint32_t pack_e4m3x4(float e0, float e1, float e2, float e3) {
    uint16_t lo, hi;   // cvt packs: d = {a_hi_byte, b_lo_byte}
    asm("cvt.rn.satfinite.e4m3x2.f32 %0, %1, %2;" : "=h"(lo) : "f"(e1), "f"(e0));
    asm("cvt.rn.satfinite.e4m3x2.f32 %0, %1, %2;" : "=h"(hi) : "f"(e3), "f"(e2));
    return (uint32_t)lo | ((uint32_t)hi << 16);
}
#define CP_ASYNC16(sa, ga) \
    asm volatile("cp.async.cg.shared.global [%0], [%1], 16;" :: "r"(sa), "l"(ga) : "memory")
#define CP_COMMIT()  asm volatile("cp.async.commit_group;" ::: "memory")
#define CP_WAIT0()   asm volatile("cp.async.wait_group 0;" ::: "memory")

// ---------------------------------------------------------------------------
// One warp per row: softmax stats, hi/lo bf16 splits, normalized e4m3
// embeddings (x16 scale), plus block-reduced usage/entropy/efficiency.
__global__ void __launch_bounds__(BDIM)
prep_kernel(const float* __restrict__ rp, const float* __restrict__ emb,
            int B, int H) {
    __shared__ float s_usage[NE];
    __shared__ float s_ent, s_eff;
    int tid = threadIdx.x;
    if (tid < NE) s_usage[tid] = 0.f;
    if (tid == 0) { s_ent = 0.f; s_eff = 0.f; }
    __syncthreads();

    int lane = tid & 31;
    int row  = blockIdx.x * (BDIM / 32) + (tid >> 5);

    const float* prow = rp + (size_t)row * NE;
    float p  = (lane < NE) ? prow[lane] : 0.f;
    float pm = (lane < NE) ? p : -1e30f;
    #pragma unroll
    for (int o = 8; o; o >>= 1) pm = fmaxf(pm, __shfl_xor_sync(0xffffffffu, pm, o));
    float ex = (lane < NE) ? expf(p - pm) : 0.f;
    float s  = ex;
    #pragma unroll
    for (int o = 8; o; o >>= 1) s += __shfl_xor_sync(0xffffffffu, s, o);
    float lse = logf(s);
    float lp  = p - pm - lse;
    float qv  = expf(lp);
    float ne   = (lane < NE) ? qv * lp : 0.f;
    float entp = (lane < NE) ? p * logf(p + 1e-8f) : 0.f;
    float effp = (lane < NE && p < 0.1f) ? p : 0.f;
    #pragma unroll
    for (int o = 8; o; o >>= 1) {
        ne   += __shfl_xor_sync(0xffffffffu, ne, o);
        entp += __shfl_xor_sync(0xffffffffu, entp, o);
        effp += __shfl_xor_sync(0xffffffffu, effp, o);
    }
    if (lane < NE) {
        __nv_bfloat16 lph = __float2bfloat16(lp);
        __nv_bfloat16 lpl = __float2bfloat16(lp - __bfloat162float(lph));
        __nv_bfloat16 qh  = __float2bfloat16(qv);
        __nv_bfloat16 ql  = __float2bfloat16(qv - __bfloat162float(qh));
        size_t b = (size_t)row * 64;
        g_pq[b + lane]      = lph;
        g_pq[b + 16 + lane] = lpl;
        g_pq[b + 32 + lane] = qh;
        g_pq[b + 48 + lane] = ql;
        atomicAdd(&s_usage[lane], p);
    }
    if (lane == 0) {
        g_negent[row] = ne;
        atomicAdd(&s_ent, entp);
        atomicAdd(&s_eff, effp);
    }

    // normalize embedding -> e4m3 (x16 scale; sim scaled x256, sign intact)
    const float4* erow4 = (const float4*)(emb + (size_t)row * H);
    float4 v[8];
    float ss = 0.f;
    #pragma unroll
    for (int i = 0; i < 8; ++i) {
        v[i] = erow4[lane + i * 32];
        ss += v[i].x * v[i].x + v[i].y * v[i].y + v[i].z * v[i].z + v[i].w * v[i].w;
    }
    #pragma unroll
    for (int o = 16; o; o >>= 1) ss += __shfl_xor_sync(0xffffffffu, ss, o);
    float inv = 16.f / sqrtf(ss);
    uint32_t* nrow = g_nemb8 + (size_t)row * (HDIM / 4);
    #pragma unroll
    for (int i = 0; i < 8; ++i) {
        nrow[lane + i * 32] = pack_e4m3x4(v[i].x * inv, v[i].y * inv,
                                          v[i].z * inv, v[i].w * inv);
    }

    __syncthreads();
    if (tid < NE) atomicAdd(&g_usage[tid], s_usage[tid]);
    if (tid == 0) { atomicAdd(&g_ent, s_ent); atomicAdd(&g_eff, s_eff); }
}

// ---------------------------------------------------------------------------
// Persistent CTAs: each loops over 128x128 upper-triangle tiles.
// e4m3 K=32 mma gram + masked bf16 KL epilogue; 8 warps 4x2, 32x64 per warp;
// 2-stage cp.async; 2 CTAs/SM; pq tiles staged overlapped with the last chunk.
// Last tile to finish computes the final loss and re-zeros global state.
__global__ void __launch_bounds__(BDIM, 2)
pairs_kernel(int B, int H, float* __restrict__ out, int ntiles) {
    extern __shared__ char smem[];
    uint32_t sb = smem_u32(smem);
    const int tid  = threadIdx.x;
    const int wid  = tid >> 5;
    const int lane = tid & 31;
    const int wm   = wid >> 1;       // 0..3 (M)
    const int wn   = wid & 1;        // 0..1 (N)
    const int nT   = B / TILE;

    // hoisted XOR-affine ldsm addressing (bit-exact vs per-ldsm recompute):
    // old offset ((row*8 + ((2s+lu) ^ (row&7))) << 4); since bit0 of 2s is 0
    // and lu in {0,1}: 2s+lu = 2s^lu, row&7 = lane&7 for all fragment rows.
    const int lrow = ((lane >> 3) & 1) * 8 + (lane & 7);
    const uint32_t vx = ((uint32_t)(lane >> 4)) ^ ((uint32_t)(lane & 7));
    uint32_t SA[2], SB[4];
    #pragma unroll
    for (int f = 0; f < 2; ++f)
        SA[f] = (uint32_t)(wm * 32 + f * 16 + lrow) * 128;
    #pragma unroll
    for (int nb = 0; nb < 4; ++nb)
        SB[nb] = 16384u + (uint32_t)(wn * 64 + nb * 16 + lrow) * 128;

    __shared__ float wsum[8];
    __shared__ int   wcnt[8];
    __shared__ int   s_last;

    for (int t = blockIdx.x; t < ntiles; t += gridDim.x) {
        int I = 0, rem = t;
        while (rem >= nT - I) { rem -= nT - I; I++; }
        int J = I + rem;             // I <= J

        if (tid < TILE) {
            *(float*)(smem + NEI_OFF + tid * 4) = g_negent[I * TILE + tid];
            *(float*)(smem + NEJ_OFF + tid * 4) = g_negent[J * TILE + tid];
        }

        const uint8_t* Agb = (const uint8_t*)g_nemb8 + (size_t)(I * TILE) * HDIM;
        const uint8_t* Bgb = (const uint8_t*)g_nemb8 + (size_t)(J * TILE) * HDIM;

        auto load_chunk = [&](int c, int stage) {
            uint32_t soff = sb + stage * STAGE_BYTES;
            const uint8_t* Ag = Agb + c * KCB;
            const uint8_t* Bg = Bgb + c * KCB;
            #pragma unroll
            for (int k = 0; k < 8; ++k) {
                int idx = tid + k * BDIM;            // 0..2047
                int tt = idx >> 10;                  // 0 = A, 1 = B
                int r = (idx >> 3) & 127;
                int u = idx & 7;
                const uint8_t* g = (tt ? Bg : Ag) + (size_t)r * HDIM + u * 16;
                uint32_t sa = soff + tt * 16384 + ((r * 8 + (u ^ (r & 7))) << 4);
                CP_ASYNC16(sa, g);
            }
        };

        float acc[2][8][4];
        #pragma unroll
        for (int f = 0; f < 2; ++f)
            #pragma unroll
            for (int n8 = 0; n8 < 8; ++n8)
                #pragma unroll
                for (int ci = 0; ci < 4; ++ci) acc[f][n8][ci] = 0.f;

        auto compute_chunk = [&](int stage) {
            uint32_t sbase = sb + stage * STAGE_BYTES;
            #pragma unroll
            for (int s = 0; s < 4; ++s) {          // 4 K=32 steps (32B each)
                uint32_t w = (((uint32_t)(2 * s)) ^ vx) << 4;
                uint32_t af[2][4];
                ldsm4(af[0], sbase + SA[0] + w);
                ldsm4(af[1], sbase + SA[1] + w);
                uint32_t bfr[4][4];
                ldsm4(bfr[0], sbase + SB[0] + w);
                ldsm4(bfr[1], sbase + SB[1] + w);
                ldsm4(bfr[2], sbase + SB[2] + w);
                ldsm4(bfr[3], sbase + SB[3] + w);
                #pragma unroll
                for (int f = 0; f < 2; ++f)
                    #pragma unroll
                    for (int nb = 0; nb < 4; ++nb) {
                        mma16832e4(acc[f][nb * 2 + 0], af[f], bfr[nb][0], bfr[nb][2]);
                        mma16832e4(acc[f][nb * 2 + 1], af[f], bfr[nb][1], bfr[nb][3]);
                    }
            }
        };

        const int NCHUNK = HDIM / KCB;   // 8
        load_chunk(0, 0); CP_COMMIT();
        #pragma unroll 1
        for (int c = 0; c < NCHUNK; ++c) {
            CP_WAIT0();
            __syncthreads();         // chunk c visible; all warps done with stage (c-1)&1
            if (c + 1 < NCHUNK) {
                load_chunk(c + 1, (c + 1) & 1);
                CP_COMMIT();
            } else {
                // stage pq tiles into the free stage-0 overlay, overlapped with
                // the final chunk's compute (stage 0's last reader was chunk 6).
                const uint8_t* pqI = (const uint8_t*)(g_pq + (size_t)(I * TILE) * 64);
                const uint8_t* pqJ = (const uint8_t*)(g_pq + (size_t)(J * TILE) * 64);
                #pragma unroll
                for (int k = 0; k < 8; ++k) {
                    int idx = tid + k * BDIM;        // 0..2047
                    int side = idx >> 10;            // 0 = I, 1 = J
                    int r2   = idx & 1023;
                    int r    = r2 >> 3;
                    int s    = r2 & 7;
                    int sec = s >> 1, half = s & 1;  // 0 lp_hi,1 lp_lo,2 q_hi,3 q_lo
                    const uint8_t* src = (side ? pqJ : pqI) + r * 128 + sec * 32 + half * 16;
                    uint32_t dst = sb + PQ_OFF + (uint32_t)(side * 4 + sec) * 4096
                                 + (uint32_t)r * 32 + (uint32_t)half * 16;
                    CP_ASYNC16(dst, src);
                }
                CP_COMMIT();
            }
            compute_chunk(c & 1);
        }
        CP_WAIT0();                  // pq staging landed
        __syncthreads();

        // ---- epilogue: mask from sim sign, ne sums, then mma KL dots ------
        const float* neI = (const float*)(smem + NEI_OFF);
        const float* neJ = (const float*)(smem + NEJ_OFF);
        int g  = lane >> 2, tg = lane & 3;
        uint64_t mask = 0ull;
        float cons = 0.f;
        #pragma unroll
        for (int f = 0; f < 2; ++f) {
            int rl = wm * 32 + f * 16 + g;
            #pragma unroll
            for (int n8 = 0; n8 < 8; ++n8) {
                int c0 = wn * 64 + n8 * 8 + tg * 2;
                #pragma unroll
                for (int ci = 0; ci < 4; ++ci) {
                    int rr = rl + (ci >> 1) * 8;
                    int cc = c0 + (ci & 1);
                    if (acc[f][n8][ci] > 0.f && (I != J || rr < cc)) {
                        mask |= 1ull << ((f * 8 + n8) * 4 + ci);
                        cons += neI[rr] + neJ[cc];
                    }
                }
            }
        }
        int cnt = 2 * __popcll(mask);    // ordered pairs

        auto pq_pass = [&](int atile, int btile, float (*kl)[8][4]) {
            uint32_t ab = sb + PQ_OFF + atile * 4096;
            uint32_t bb = sb + PQ_OFF + btile * 4096;
            int lu16 = (lane >> 4) * 16;
            uint32_t af[2][4];
            #pragma unroll
            for (int f = 0; f < 2; ++f)
                ldsm4(af[f], ab + (wm * 32 + f * 16 + lrow) * 32 + lu16);
            #pragma unroll
            for (int nb = 0; nb < 4; ++nb) {
                uint32_t b4[4];
                ldsm4(b4, bb + (wn * 64 + nb * 16 + lrow) * 32 + lu16);
                #pragma unroll
                for (int f = 0; f < 2; ++f) {
                    mma16816(kl[f][nb * 2 + 0], af[f], b4[0], b4[2]);
                    mma16816(kl[f][nb * 2 + 1], af[f], b4[1], b4[3]);
                }
            }
        };

        {
            float kl[2][8][4] = {};
            pq_pass(0, 6, kl);   // lpI_hi . qJ_hi
            pq_pass(1, 6, kl);   // lpI_lo . qJ_hi
            pq_pass(0, 7, kl);   // lpI_hi . qJ_lo
            #pragma unroll
            for (int f = 0; f < 2; ++f)
                #pragma unroll
                for (int n8 = 0; n8 < 8; ++n8)
                    #pragma unroll
                    for (int ci = 0; ci < 4; ++ci) {
                        if ((mask >> ((f * 8 + n8) * 4 + ci)) & 1ull)
                            cons -= kl[f][n8][ci];
                        kl[f][n8][ci] = 0.f;
                    }
            pq_pass(2, 4, kl);   // qI_hi . lpJ_hi
            pq_pass(3, 4, kl);   // qI_lo . lpJ_hi
            pq_pass(2, 5, kl);   // qI_hi . lpJ_lo
            #pragma unroll
            for (int f = 0; f < 2; ++f)
                #pragma unroll
                for (int n8 = 0; n8 < 8; ++n8)
                    #pragma unroll
                    for (int ci = 0; ci < 4; ++ci)
                        if ((mask >> ((f * 8 + n8) * 4 + ci)) & 1ull)
                            cons -= kl[f][n8][ci];
        }

        // ---- block reduce + atomics ---------------------------------------
        #pragma unroll
        for (int o = 16; o; o >>= 1) {
            cons += __shfl_xor_sync(0xffffffffu, cons, o);
            cnt  += __shfl_xor_sync(0xffffffffu, cnt, o);
        }
        if (lane == 0) { wsum[wid] = cons; wcnt[wid] = cnt; }
        __syncthreads();             // also: all warps done reading ne/pq smem
        if (tid == 0) {
            float cs = 0.f; int cc = 0;
            #pragma unroll
            for (int w = 0; w < 8; w++) { cs += wsum[w]; cc += wcnt[w]; }
            atomicAdd(&g_cons, cs);
            atomicAdd(&g_pairs, (unsigned long long)cc);
            __threadfence();
            unsigned int old = atomicAdd(&g_done, 1u);
            s_last = (old == (unsigned int)(ntiles - 1));
        }
        __syncthreads();

        // ---- last tile: finalize + re-zero state for the next replay ------
        if (s_last && tid == 0) {
            float invB = 1.f / (float)B;
            float u[NE], mean = 0.f;
            #pragma unroll
            for (int e = 0; e < NE; e++) { u[e] = g_usage[e] * invB; mean += u[e]; }
            mean /= (float)NE;
            float var = 0.f;
            #pragma unroll
            for (int e = 0; e < NE; e++) { float d = u[e] - mean; var += d * d; }
            var /= (float)(NE - 1);
            float load_balance = var * (float)(NE * NE);
            float entropy_loss = g_ent * invB;
            float efficiency   = g_eff * invB;
            unsigned long long np = g_pairs;
            float consf = (np > 0) ? (g_cons / (float)np) : 0.f;
            out[0] = load_balance + entropy_loss + efficiency + consf;
            // reset accumulators so every graph replay starts clean
            g_cons = 0.f; g_ent = 0.f; g_eff = 0.f; g_pairs = 0ull;
            #pragma unroll
            for (int e = 0; e < NE; e++) g_usage[e] = 0.f;
            g_done = 0u;
        }
        __syncthreads();             // s_last / smem safe for next tile
    }
}

// ---------------------------------------------------------------------------
extern "C" void kernel_launch(void* const* d_in, const int* in_sizes, int n_in,
                              void* d_out, int out_size) {
    const float* rp  = (const float*)d_in[0];
    const float* emb = (const float*)d_in[1];
    float* out = (float*)d_out;
    int B = in_sizes[0] / NE;        // 4096
    int H = in_sizes[1] / B;         // 1024

    cudaFuncSetAttribute(pairs_kernel,
                         cudaFuncAttributeMaxDynamicSharedMemorySize, SMEM_BYTES);

    prep_kernel<<<B / (BDIM / 32), BDIM>>>(rp, emb, B, H);
    int nT = B / TILE;
    int ntiles = nT * (nT + 1) / 2;  // 528
    int grid = ntiles < MAXCTAS ? ntiles : MAXCTAS;
    pairs_kernel<<<grid, BDIM, SMEM_BYTES>>>(B, H, out, ntiles);
}